// round 1
// baseline (speedup 1.0000x reference)
#include <cuda_runtime.h>
#include <math.h>

#define BATCH    512
#define FDIM     128
#define KNEG     4096
#define NDATA    1200000
#define INV_TEMP (1.0f/0.07f)
#define EPSN     1e-12f

// scratch (device globals: no allocation allowed)
__device__ float g_s[BATCH * FDIM];      // normalized student
__device__ float g_t[BATCH * FDIM];      // normalized teacher
__device__ float g_pos[BATCH];           // positive logits
__device__ float g_sumexp[BATCH];        // sum exp(logit - M), M = 1/TEMP

__device__ __forceinline__ float warpSum(float v) {
#pragma unroll
    for (int o = 16; o > 0; o >>= 1) v += __shfl_xor_sync(0xffffffffu, v, o);
    return v;
}

// block of 128 threads, full sum broadcast to all threads
__device__ __forceinline__ float blockSum128(float v, float* sh) {
    int w = threadIdx.x >> 5, l = threadIdx.x & 31;
    v = warpSum(v);
    if (l == 0) sh[w] = v;
    __syncthreads();
    float t = sh[0] + sh[1] + sh[2] + sh[3];
    __syncthreads();
    return t;
}

// ---------------------------------------------------------------------------
// 1) normalize s/t, pos logits, init sumexp with the positive term
// grid = BATCH blocks x 128 threads
__global__ void prep_kernel(const float* __restrict__ stu,
                            const float* __restrict__ tea) {
    __shared__ float sh[4];
    int b = blockIdx.x;
    int d = threadIdx.x;
    float sv = stu[b * FDIM + d];
    float tv = tea[b * FDIM + d];
    float sn2 = blockSum128(sv * sv, sh);
    float tn2 = blockSum128(tv * tv, sh);
    float sn = sv / fmaxf(sqrtf(sn2), EPSN);
    float tn = tv / fmaxf(sqrtf(tn2), EPSN);
    g_s[b * FDIM + d] = sn;
    g_t[b * FDIM + d] = tn;
    float pos = blockSum128(sn * tn, sh) * INV_TEMP;
    if (d == 0) {
        g_pos[b] = pos;
        g_sumexp[b] = __expf(pos - INV_TEMP);
    }
}

// ---------------------------------------------------------------------------
// 2) copy memory bank into output (out + 1 float offset => misaligned dst).
// Aligned STG.128 on out[4m..4m+3], misaligned-but-coalesced scalar loads.
__global__ void copy_bank(const float* __restrict__ src, float* __restrict__ out) {
    const long long NTOT = (long long)NDATA * FDIM;       // 153,600,000
    const long long MLAST = (NTOT - 4) / 4;               // 38,399,999
    long long tid = (long long)blockIdx.x * blockDim.x + threadIdx.x;
    long long stride = (long long)gridDim.x * blockDim.x;
    for (long long m = tid + 1; m <= MLAST; m += stride) {
        long long j = 4 * m;                               // out index, 16B-aligned
        float4 v;
        v.x = __ldg(&src[j - 1]);
        v.y = __ldg(&src[j + 0]);
        v.z = __ldg(&src[j + 1]);
        v.w = __ldg(&src[j + 2]);
        *reinterpret_cast<float4*>(out + j) = v;
    }
    if (tid == 0) {
        out[1] = src[0];
        out[2] = src[1];
        out[3] = src[2];
        out[NTOT] = src[NTOT - 1];
    }
}

// ---------------------------------------------------------------------------
// 3) EMA update + l2norm + scatter (last duplicate index wins, like JAX set)
// grid = BATCH blocks x 128 threads. outBank = out + 1
__global__ void scatter_kernel(const float* __restrict__ bank,
                               const int* __restrict__ idxs,
                               float* __restrict__ outBank) {
    __shared__ float sh[4];
    __shared__ int skip;
    int b = blockIdx.x;
    int d = threadIdx.x;
    int idx = idxs[b];
    if (d == 0) {
        int s = 0;
        for (int bb = b + 1; bb < BATCH; bb++)
            if (idxs[bb] == idx) { s = 1; break; }
        skip = s;
    }
    float u = 0.5f * bank[(long long)idx * FDIM + d] + 0.5f * g_t[b * FDIM + d];
    float n2 = blockSum128(u * u, sh);   // contains syncthreads -> skip visible
    if (!skip)
        outBank[(long long)idx * FDIM + d] = u / fmaxf(sqrtf(n2), EPSN);
}

// ---------------------------------------------------------------------------
// 4) the big gather: 2M rows x 512B. One row per warp, LDG.128 per lane,
// unroll-2 rows for MLP. 16 blocks per batch row => 256 rows/block.
#define NEG_BLOCKS_PER_B 16
#define ROWS_PER_BLOCK   (KNEG / NEG_BLOCKS_PER_B)   // 256
#define NEG_WARPS        16
__global__ __launch_bounds__(NEG_WARPS * 32)
void neg_kernel(const float* __restrict__ bank,
                const int* __restrict__ r,
                const int* __restrict__ idxs) {
    int b = blockIdx.x / NEG_BLOCKS_PER_B;
    int chunk = blockIdx.x % NEG_BLOCKS_PER_B;
    int warp = threadIdx.x >> 5, lane = threadIdx.x & 31;

    float4 s4 = *reinterpret_cast<const float4*>(&g_s[b * FDIM + lane * 4]);
    int self = idxs[b];
    int jbase = chunk * ROWS_PER_BLOCK + warp * (ROWS_PER_BLOCK / NEG_WARPS);
    const int* rb = r + (long long)b * KNEG;

    float acc = 0.0f;
#pragma unroll
    for (int i = 0; i < ROWS_PER_BLOCK / NEG_WARPS; i += 2) {
        int j0 = jbase + i;
        int rv0 = __ldg(&rb[j0]);
        int rv1 = __ldg(&rb[j0 + 1]);
        int n0 = rv0 + (rv0 >= self);
        int n1 = rv1 + (rv1 >= self);
        float4 x0 = __ldg(reinterpret_cast<const float4*>(bank + (long long)n0 * FDIM) + lane);
        float4 x1 = __ldg(reinterpret_cast<const float4*>(bank + (long long)n1 * FDIM) + lane);

        float d0 = fmaf(x0.x, s4.x, fmaf(x0.y, s4.y, fmaf(x0.z, s4.z, x0.w * s4.w)));
        float q0 = fmaf(x0.x, x0.x, fmaf(x0.y, x0.y, fmaf(x0.z, x0.z, x0.w * x0.w)));
        float d1 = fmaf(x1.x, s4.x, fmaf(x1.y, s4.y, fmaf(x1.z, s4.z, x1.w * s4.w)));
        float q1 = fmaf(x1.x, x1.x, fmaf(x1.y, x1.y, fmaf(x1.z, x1.z, x1.w * x1.w)));
#pragma unroll
        for (int o = 16; o > 0; o >>= 1) {
            d0 += __shfl_xor_sync(0xffffffffu, d0, o);
            q0 += __shfl_xor_sync(0xffffffffu, q0, o);
            d1 += __shfl_xor_sync(0xffffffffu, d1, o);
            q1 += __shfl_xor_sync(0xffffffffu, q1, o);
        }
        float l0 = d0 * rsqrtf(fmaxf(q0, 1e-24f)) * INV_TEMP;
        float l1 = d1 * rsqrtf(fmaxf(q1, 1e-24f)) * INV_TEMP;
        acc += __expf(l0 - INV_TEMP) + __expf(l1 - INV_TEMP);
    }
    __shared__ float sh[NEG_WARPS];
    if (lane == 0) sh[warp] = acc;
    __syncthreads();
    if (threadIdx.x == 0) {
        float tot = 0.0f;
#pragma unroll
        for (int w = 0; w < NEG_WARPS; w++) tot += sh[w];
        atomicAdd(&g_sumexp[b], tot);
    }
}

// ---------------------------------------------------------------------------
// 5) loss = mean( M + log(sumexp_b) - pos_b )
__global__ void finalize_kernel(float* __restrict__ out) {
    __shared__ float sh[16];
    int tid = threadIdx.x;            // 512 threads
    float v = INV_TEMP + logf(g_sumexp[tid]) - g_pos[tid];
    v = warpSum(v);
    if ((tid & 31) == 0) sh[tid >> 5] = v;
    __syncthreads();
    if (tid == 0) {
        float tot = 0.0f;
#pragma unroll
        for (int w = 0; w < 16; w++) tot += sh[w];
        out[0] = tot * (1.0f / BATCH);
    }
}

// ---------------------------------------------------------------------------
extern "C" void kernel_launch(void* const* d_in, const int* in_sizes, int n_in,
                              void* d_out, int out_size) {
    const float* stu  = (const float*)d_in[0];
    const float* tea  = (const float*)d_in[1];
    const float* bank = (const float*)d_in[2];
    const int*   idxs = (const int*)d_in[3];
    const int*   r    = (const int*)d_in[4];
    float* out = (float*)d_out;

    prep_kernel<<<BATCH, 128>>>(stu, tea);
    copy_bank<<<2048, 256>>>(bank, out);
    scatter_kernel<<<BATCH, 128>>>(bank, idxs, out + 1);
    neg_kernel<<<BATCH * NEG_BLOCKS_PER_B, NEG_WARPS * 32>>>(bank, r, idxs);
    finalize_kernel<<<1, 512>>>(out);
}